// round 2
// baseline (speedup 1.0000x reference)
#include <cuda_runtime.h>
#include <math.h>

#define BATCH 2
#define SEQ   2048
#define EMB   2048
#define NH    16
#define HD    128
#define NQKV  6144
#define MROWS 4096

// ---------------- scratch (no allocation allowed) ----------------
__device__ float g_q[BATCH * NH * SEQ * HD];     // 33.5 MB, [b,h,s,d]
__device__ float g_k[BATCH * NH * SEQ * HD];
__device__ float g_v[BATCH * NH * SEQ * HD];
__device__ float g_attn[BATCH * SEQ * EMB];      // [b,s, h*HD+d]

// =================================================================
// Tiled SGEMM: C[M,N] = A[M,K] @ W[N,K]^T + bias[N]
// 128x128 tile, BK=8, 256 threads, 8x8 per thread (4+4 split for
// conflict-free LDS.128 fragments).
// MODE 0: write C row-major (output projection -> d_out)
// MODE 1: scatter into g_q/g_k/g_v with [b,h,s,d] layout
// =================================================================
template <int MODE>
__global__ void __launch_bounds__(256)
sgemm_nt(const float* __restrict__ A, const float* __restrict__ W,
         const float* __restrict__ bias, float* __restrict__ C,
         int Kdim, int Ndim)
{
    __shared__ float As[8][128];
    __shared__ float Ws[8][128];

    const int tid = threadIdx.x;
    const int tx = tid & 15, ty = tid >> 4;
    const int bm = blockIdx.y * 128, bn = blockIdx.x * 128;

    float acc[8][8];
#pragma unroll
    for (int i = 0; i < 8; ++i)
#pragma unroll
        for (int j = 0; j < 8; ++j) acc[i][j] = 0.f;

    const int lrow = tid >> 1;          // 0..127
    const int lseg = (tid & 1) << 2;    // 0 or 4
    const float* Ag = A + (bm + lrow) * Kdim + lseg;
    const float* Wg = W + (bn + lrow) * Kdim + lseg;

    for (int k0 = 0; k0 < Kdim; k0 += 8) {
        float4 av = *(const float4*)(Ag + k0);
        float4 wv = *(const float4*)(Wg + k0);
        __syncthreads();
        As[lseg + 0][lrow] = av.x; As[lseg + 1][lrow] = av.y;
        As[lseg + 2][lrow] = av.z; As[lseg + 3][lrow] = av.w;
        Ws[lseg + 0][lrow] = wv.x; Ws[lseg + 1][lrow] = wv.y;
        Ws[lseg + 2][lrow] = wv.z; Ws[lseg + 3][lrow] = wv.w;
        __syncthreads();
#pragma unroll
        for (int kk = 0; kk < 8; ++kk) {
            float a[8], b[8];
            float4 t0 = *(const float4*)(&As[kk][ty * 4]);
            float4 t1 = *(const float4*)(&As[kk][64 + ty * 4]);
            a[0] = t0.x; a[1] = t0.y; a[2] = t0.z; a[3] = t0.w;
            a[4] = t1.x; a[5] = t1.y; a[6] = t1.z; a[7] = t1.w;
            float4 u0 = *(const float4*)(&Ws[kk][tx * 4]);
            float4 u1 = *(const float4*)(&Ws[kk][64 + tx * 4]);
            b[0] = u0.x; b[1] = u0.y; b[2] = u0.z; b[3] = u0.w;
            b[4] = u1.x; b[5] = u1.y; b[6] = u1.z; b[7] = u1.w;
#pragma unroll
            for (int i = 0; i < 8; ++i)
#pragma unroll
                for (int j = 0; j < 8; ++j)
                    acc[i][j] += a[i] * b[j];
        }
    }

    // epilogue
#pragma unroll
    for (int i = 0; i < 8; ++i) {
        const int gm = bm + ((i < 4) ? (ty * 4 + i) : (64 + ty * 4 + i - 4));
#pragma unroll
        for (int jj = 0; jj < 2; ++jj) {
            const int gn = bn + ((jj == 0) ? (tx * 4) : (64 + tx * 4));
            float4 bb = *(const float4*)(bias + gn);
            float4 v;
            v.x = acc[i][jj * 4 + 0] + bb.x;
            v.y = acc[i][jj * 4 + 1] + bb.y;
            v.z = acc[i][jj * 4 + 2] + bb.z;
            v.w = acc[i][jj * 4 + 3] + bb.w;
            if (MODE == 0) {
                *(float4*)(C + gm * Ndim + gn) = v;
            } else {
                const int b = gm >> 11, s = gm & 2047;       // SEQ=2048
                const int which = gn >> 11;                  // EMB=2048
                const int rr = gn & 2047;
                const int hh = rr >> 7, dd = rr & 127;       // HD=128
                float* dst = (which == 0) ? g_q : (which == 1 ? g_k : g_v);
                *(float4*)(dst + (((b * NH + hh) * SEQ + s) * HD + dd)) = v;
            }
        }
    }
}

// =================================================================
// RoPE exactly as the reference:
//   cos/sin tables: freqs[t, d] = t * angle[d/2], angle[i] = 10000^(-(2i)/EMB)
//   trans: out[d<64] = -x[2d+1] ; out[d>=64] = x[2(d-64)]
// Applied in-place to g_q and g_k. One block per row (128 threads).
// =================================================================
__global__ void rope_kernel()
{
    __shared__ float rq[HD], rk[HD];
    const int row = blockIdx.x;            // (b*NH+h)*SEQ + s
    const int s = row & (SEQ - 1);
    const int d = threadIdx.x;
    float* qp = g_q + row * HD;
    float* kp = g_k + row * HD;
    rq[d] = qp[d];
    rk[d] = kp[d];
    __syncthreads();

    const int i = d >> 1;
    // double-precision table to stay within fp32-reference tolerance
    const double ang = exp(-((double)(2 * i) / 2048.0) * 9.210340371976184); // ln(1e4)
    const double fr = (double)s * ang;
    const float c  = (float)cos(fr);
    const float sn = (float)sin(fr);

    float oq, ok;
    if (d < 64) {
        oq = c * rq[d] - sn * rq[2 * d + 1];
        ok = c * rk[d] - sn * rk[2 * d + 1];
    } else {
        const int j = d - 64;
        oq = c * rq[d] + sn * rq[2 * j];
        ok = c * rk[d] + sn * rk[2 * j];
    }
    qp[d] = oq;
    kp[d] = ok;
}

// =================================================================
// Flash attention: one block per (b, h, 64-row q-tile). 256 threads.
// smem: Qs/Ks transposed [d][m] (stride 68), Vs [k][d] (stride 132),
// Ps transposed [k][m] (stride 68), per-row m/l/scale state.
// =================================================================
#define QK_STRIDE 68
#define V_STRIDE  132
#define P_STRIDE  68
#define ATTN_SMEM ((128 * QK_STRIDE * 2 + 64 * V_STRIDE + 64 * P_STRIDE + 256) * 4)

__global__ void __launch_bounds__(256)
attn_kernel(const int* __restrict__ mask)
{
    extern __shared__ float sm[];
    float* Qs   = sm;                         // [128][68]
    float* Ks   = Qs + 128 * QK_STRIDE;       // [128][68]
    float* Vs   = Ks + 128 * QK_STRIDE;       // [64][132]
    float* Ps   = Vs + 64 * V_STRIDE;         // [64][68]  (Ps[k][m])
    float* marr = Ps + 64 * P_STRIDE;
    float* larr = marr + 64;
    float* scl  = larr + 64;
    float* mskv = scl + 64;

    const int tid = threadIdx.x;
    const int tx = tid & 15, ty = tid >> 4;
    const int q0 = blockIdx.x * 64;
    const int h = blockIdx.y, b = blockIdx.z;

    const float* qbase = g_q + ((b * NH + h) * SEQ + q0) * HD;
    const float* kbase = g_k + ((b * NH + h) * SEQ) * HD;
    const float* vbase = g_v + ((b * NH + h) * SEQ) * HD;
    const float SCALE = 0.08838834764831845f;  // 1/sqrt(128)

    // load Q tile transposed, pre-scaled
#pragma unroll
    for (int r = 0; r < 8; ++r) {
        const int idx = tid + r * 256;        // 0..2047
        const int m = idx >> 5;               // 0..63
        const int dsg = (idx & 31) << 2;      // 0..124
        float4 v = *(const float4*)(qbase + m * HD + dsg);
        Qs[(dsg + 0) * QK_STRIDE + m] = v.x * SCALE;
        Qs[(dsg + 1) * QK_STRIDE + m] = v.y * SCALE;
        Qs[(dsg + 2) * QK_STRIDE + m] = v.z * SCALE;
        Qs[(dsg + 3) * QK_STRIDE + m] = v.w * SCALE;
    }
    if (tid < 64) { marr[tid] = -INFINITY; larr[tid] = 0.f; }

    float acc[4][8];
#pragma unroll
    for (int i = 0; i < 4; ++i)
#pragma unroll
        for (int j = 0; j < 8; ++j) acc[i][j] = 0.f;

    for (int kt = 0; kt < SEQ / 64; ++kt) {
        __syncthreads();   // previous stage-2 done reading Ks/Vs/Ps; state ready
        const float* kb = kbase + kt * 64 * HD;
        const float* vb = vbase + kt * 64 * HD;
#pragma unroll
        for (int r = 0; r < 8; ++r) {
            const int idx = tid + r * 256;
            const int m = idx >> 5;
            const int dsg = (idx & 31) << 2;
            float4 kv = *(const float4*)(kb + m * HD + dsg);
            Ks[(dsg + 0) * QK_STRIDE + m] = kv.x;
            Ks[(dsg + 1) * QK_STRIDE + m] = kv.y;
            Ks[(dsg + 2) * QK_STRIDE + m] = kv.z;
            Ks[(dsg + 3) * QK_STRIDE + m] = kv.w;
            float4 vv = *(const float4*)(vb + m * HD + dsg);
            *(float4*)(Vs + m * V_STRIDE + dsg) = vv;
        }
        if (tid < 64) mskv[tid] = (float)mask[b * SEQ + kt * 64 + tid];
        __syncthreads();

        // ---- stage 1: S = Q @ K^T (each thread 4x4) ----
        float sa[4][4];
#pragma unroll
        for (int i = 0; i < 4; ++i)
#pragma unroll
            for (int j = 0; j < 4; ++j) sa[i][j] = 0.f;
#pragma unroll 4
        for (int d = 0; d < 128; ++d) {
            float4 a  = *(const float4*)(Qs + d * QK_STRIDE + ty * 4);
            float4 bb = *(const float4*)(Ks + d * QK_STRIDE + tx * 4);
            float av[4] = {a.x, a.y, a.z, a.w};
            float bv[4] = {bb.x, bb.y, bb.z, bb.w};
#pragma unroll
            for (int i = 0; i < 4; ++i)
#pragma unroll
                for (int j = 0; j < 4; ++j)
                    sa[i][j] += av[i] * bv[j];
        }

        // mask + online softmax
        float msk[4];
#pragma unroll
        for (int j = 0; j < 4; ++j) msk[j] = mskv[tx * 4 + j];
#pragma unroll
        for (int i = 0; i < 4; ++i) {
#pragma unroll
            for (int j = 0; j < 4; ++j)
                if (msk[j] == 0.f) sa[i][j] = -1e9f;
            float rm = fmaxf(fmaxf(sa[i][0], sa[i][1]), fmaxf(sa[i][2], sa[i][3]));
            rm = fmaxf(rm, __shfl_xor_sync(0xffffffffu, rm, 8, 16));
            rm = fmaxf(rm, __shfl_xor_sync(0xffffffffu, rm, 4, 16));
            rm = fmaxf(rm, __shfl_xor_sync(0xffffffffu, rm, 2, 16));
            rm = fmaxf(rm, __shfl_xor_sync(0xffffffffu, rm, 1, 16));
            const int rowi = ty * 4 + i;
            const float mo = marr[rowi];
            const float mn = fmaxf(mo, rm);
            float rs = 0.f;
#pragma unroll
            for (int j = 0; j < 4; ++j) {
                float p = __expf(sa[i][j] - mn);
                Ps[(tx * 4 + j) * P_STRIDE + rowi] = p;
                rs += p;
            }
            rs += __shfl_xor_sync(0xffffffffu, rs, 8, 16);
            rs += __shfl_xor_sync(0xffffffffu, rs, 4, 16);
            rs += __shfl_xor_sync(0xffffffffu, rs, 2, 16);
            rs += __shfl_xor_sync(0xffffffffu, rs, 1, 16);
            if (tx == 0) {
                const float sc = (mo == -INFINITY) ? 0.f : __expf(mo - mn);
                scl[rowi]  = sc;
                larr[rowi] = larr[rowi] * sc + rs;
                marr[rowi] = mn;
            }
        }
        __syncthreads();

        // ---- stage 2: O = O*scale + P @ V ----
        float sc[4];
#pragma unroll
        for (int i = 0; i < 4; ++i) sc[i] = scl[ty * 4 + i];
#pragma unroll
        for (int i = 0; i < 4; ++i)
#pragma unroll
            for (int j = 0; j < 8; ++j) acc[i][j] *= sc[i];

#pragma unroll 4
        for (int k = 0; k < 64; ++k) {
            float4 a  = *(const float4*)(Ps + k * P_STRIDE + ty * 4);
            float4 b0 = *(const float4*)(Vs + k * V_STRIDE + tx * 4);
            float4 b1 = *(const float4*)(Vs + k * V_STRIDE + 64 + tx * 4);
            float av[4] = {a.x, a.y, a.z, a.w};
            float bv[8] = {b0.x, b0.y, b0.z, b0.w, b1.x, b1.y, b1.z, b1.w};
#pragma unroll
            for (int i = 0; i < 4; ++i)
#pragma unroll
                for (int j = 0; j < 8; ++j)
                    acc[i][j] += av[i] * bv[j];
        }
    }

    // final normalize + write (cols tx*4..+3 and 64+tx*4..+3)
#pragma unroll
    for (int i = 0; i < 4; ++i) {
        const float inv = 1.f / larr[ty * 4 + i];
        const int qrow = q0 + ty * 4 + i;
        float* obase = g_attn + (b * SEQ + qrow) * EMB + h * HD;
        float4 v0, v1;
        v0.x = acc[i][0] * inv; v0.y = acc[i][1] * inv;
        v0.z = acc[i][2] * inv; v0.w = acc[i][3] * inv;
        v1.x = acc[i][4] * inv; v1.y = acc[i][5] * inv;
        v1.z = acc[i][6] * inv; v1.w = acc[i][7] * inv;
        *(float4*)(obase + tx * 4) = v0;
        *(float4*)(obase + 64 + tx * 4) = v1;
    }
}

// =================================================================
extern "C" void kernel_launch(void* const* d_in, const int* in_sizes, int n_in,
                              void* d_out, int out_size)
{
    const float* X    = (const float*)d_in[0];
    const int*   mask = (const int*)d_in[1];
    const float* Wqkv = (const float*)d_in[2];
    const float* bqkv = (const float*)d_in[3];
    const float* Wo   = (const float*)d_in[4];
    const float* bo   = (const float*)d_in[5];
    float* out = (float*)d_out;

    float* dAttn = nullptr;
    cudaGetSymbolAddress((void**)&dAttn, g_attn);

    // 1) QKV projection + scatter to [b,h,s,d]
    sgemm_nt<1><<<dim3(NQKV / 128, MROWS / 128), 256>>>(X, Wqkv, bqkv, nullptr, EMB, NQKV);

    // 2) RoPE in-place on Q and K
    rope_kernel<<<BATCH * NH * SEQ, 128>>>();

    // 3) flash attention
    cudaFuncSetAttribute(attn_kernel, cudaFuncAttributeMaxDynamicSharedMemorySize, ATTN_SMEM);
    attn_kernel<<<dim3(SEQ / 64, NH, BATCH), 256, ATTN_SMEM>>>(mask);

    // 4) output projection
    sgemm_nt<0><<<dim3(EMB / 128, MROWS / 128), 256>>>(dAttn, Wo, bo, out, EMB, EMB);
}

// round 8
// speedup vs baseline: 2.2275x; 2.2275x over previous
#include <cuda_runtime.h>
#include <cuda_bf16.h>
#include <math.h>
#include <stdint.h>

#define BATCH 2
#define SEQ   2048
#define EMB   2048
#define NH    16
#define HD    128
#define NQKV  6144
#define MROWS 4096
#define GK    2048
#define NSTG  (GK / 32)     // 64 stages of BK=32

// ---------------- scratch (no allocation allowed) ----------------
__device__ float g_q[BATCH * NH * SEQ * HD];
__device__ float g_k[BATCH * NH * SEQ * HD];
__device__ float g_v[BATCH * NH * SEQ * HD];
__device__ float g_attn[BATCH * SEQ * EMB];

__device__ __nv_bfloat16 g_ahi[MROWS * GK];     // X, later attn output
__device__ __nv_bfloat16 g_alo[MROWS * GK];
__device__ __nv_bfloat16 g_w1hi[NQKV * GK];
__device__ __nv_bfloat16 g_w1lo[NQKV * GK];
__device__ __nv_bfloat16 g_w2hi[EMB * GK];
__device__ __nv_bfloat16 g_w2lo[EMB * GK];

// ================= family-generic PTX helpers ====================
__device__ __forceinline__ uint32_t smem_u32(const void* p) {
    uint32_t a;
    asm("{ .reg .u64 t; cvta.to.shared.u64 t, %1; cvt.u32.u64 %0, t; }" : "=r"(a) : "l"(p));
    return a;
}
#define CP_ASYNC16(s, g) \
    asm volatile("cp.async.cg.shared.global [%0], [%1], 16;" :: "r"(s), "l"(g))
#define CP_COMMIT() asm volatile("cp.async.commit_group;" ::: "memory")
#define CP_WAIT1()  asm volatile("cp.async.wait_group 1;" ::: "memory")
#define CP_WAIT0()  asm volatile("cp.async.wait_group 0;" ::: "memory")

__device__ __forceinline__ void ldsm4(uint32_t* r, uint32_t addr) {
    asm volatile("ldmatrix.sync.aligned.m8n8.x4.shared.b16 {%0,%1,%2,%3}, [%4];"
        : "=r"(r[0]), "=r"(r[1]), "=r"(r[2]), "=r"(r[3]) : "r"(addr));
}
__device__ __forceinline__ void mma_bf16(float* c, const uint32_t* a, const uint32_t* b) {
    asm volatile(
        "mma.sync.aligned.m16n8k16.row.col.f32.bf16.bf16.f32 "
        "{%0,%1,%2,%3}, {%4,%5,%6,%7}, {%8,%9}, {%0,%1,%2,%3};"
        : "+f"(c[0]), "+f"(c[1]), "+f"(c[2]), "+f"(c[3])
        : "r"(a[0]), "r"(a[1]), "r"(a[2]), "r"(a[3]), "r"(b[0]), "r"(b[1]));
}

// ================= fp32 -> bf16 hi/lo split ======================
__global__ void cvt_split(const float* __restrict__ x,
                          __nv_bfloat16* __restrict__ hi,
                          __nv_bfloat16* __restrict__ lo, int n)
{
    int i = (blockIdx.x * blockDim.x + threadIdx.x) * 4;
    if (i >= n) return;
    float4 v = *(const float4*)(x + i);
    __nv_bfloat16 h0 = __float2bfloat16(v.x);
    __nv_bfloat16 h1 = __float2bfloat16(v.y);
    __nv_bfloat16 h2 = __float2bfloat16(v.z);
    __nv_bfloat16 h3 = __float2bfloat16(v.w);
    __nv_bfloat16 l0 = __float2bfloat16(v.x - __bfloat162float(h0));
    __nv_bfloat16 l1 = __float2bfloat16(v.y - __bfloat162float(h1));
    __nv_bfloat16 l2 = __float2bfloat16(v.z - __bfloat162float(h2));
    __nv_bfloat16 l3 = __float2bfloat16(v.w - __bfloat162float(h3));
    __nv_bfloat162 a, b, c, d;
    a.x = h0; a.y = h1; b.x = h2; b.y = h3;
    c.x = l0; c.y = l1; d.x = l2; d.y = l3;
    *(__nv_bfloat162*)(hi + i)     = a;
    *(__nv_bfloat162*)(hi + i + 2) = b;
    *(__nv_bfloat162*)(lo + i)     = c;
    *(__nv_bfloat162*)(lo + i + 2) = d;
}

// =================================================================
// mma.sync bf16x3 GEMM: C[M,N] = A[M,K] @ B[N,K]^T + bias
// 128x128 CTA tile, BK=32, cp.async double-buffered SMEM.
// 8 warps, warp tile 64x32 (2x4 warp grid), m16n8k16 HMMA.
// SMEM tiles: [128 rows][40 bf16] (80B stride: 16B-aligned, ldmatrix
// conflict-free: 20-word stride -> banks {0,20,8,28,16,4,24,12}).
// MODE 0: row-major C     MODE 1: scatter to g_q/g_k/g_v [b,h,s,d]
// =================================================================
#define SROWB 80                 // bytes per smem row
#define MATB  (128 * SROWB)      // 10240 B per matrix tile
#define BUFB  (4 * MATB)         // 40960 B per stage buffer
#define GEMM_SMEM (2 * BUFB)     // 81920 B

template <int MODE>
__global__ void __launch_bounds__(256, 1)
gemm_mma(const __nv_bfloat16* __restrict__ Ahi, const __nv_bfloat16* __restrict__ Alo,
         const __nv_bfloat16* __restrict__ Bhi, const __nv_bfloat16* __restrict__ Blo,
         const float* __restrict__ bias, float* __restrict__ C, int Ndim)
{
    extern __shared__ char smem[];
    const uint32_t sb = smem_u32(smem);
    const int tid = threadIdx.x;
    const int lane = tid & 31, wid = tid >> 5;
    const int wm = wid >> 2, wn = wid & 3;          // warp grid 2x4
    const int bm = blockIdx.y * 128, bn = blockIdx.x * 128;

    const char* gA0 = (const char*)(Ahi + (size_t)bm * GK);
    const char* gA1 = (const char*)(Alo + (size_t)bm * GK);
    const char* gB0 = (const char*)(Bhi + (size_t)bn * GK);
    const char* gB1 = (const char*)(Blo + (size_t)bn * GK);

    // loader assignment: 512 16B-chunks per matrix, 2 per thread
    const int lrow0 = tid >> 2;
    const int lrow1 = 64 + (tid >> 2);
    const int lseg  = (tid & 3) * 16;               // 0..48 bytes (32 bf16/row)

    // ldmatrix address offsets (within a matrix tile)
    // A frag (16x16 at m-tile mt): row = wm*64 + mt*16 + (lane&15), khalf = (lane>>4)*8
    uint32_t arow[4];
#pragma unroll
    for (int mt = 0; mt < 4; ++mt)
        arow[mt] = (uint32_t)((wm * 64 + mt * 16 + (lane & 15)) * SROWB + ((lane >> 4) << 4));
    // B frag (k16 x n16 at n-block nb): row = wn*32 + nb*16 + ((lane>>4)<<3) + (lane&7),
    //                                   khalf = ((lane>>3)&1)*8
    uint32_t brow[2];
#pragma unroll
    for (int nb = 0; nb < 2; ++nb)
        brow[nb] = (uint32_t)((wn * 32 + nb * 16 + ((lane >> 4) << 3) + (lane & 7)) * SROWB
                              + (((lane >> 3) & 1) << 4));

    float acc[4][4][4];
#pragma unroll
    for (int i = 0; i < 4; ++i)
#pragma unroll
        for (int j = 0; j < 4; ++j)
#pragma unroll
            for (int k = 0; k < 4; ++k) acc[i][j][k] = 0.f;

    auto issue_load = [&](int stage, int buf) {
        const size_t kb = (size_t)stage * 64;       // BK=32 bf16 = 64 bytes
        const uint32_t sbase = sb + buf * BUFB + lseg;
        const size_t go = kb + lseg;
        const size_t r0 = (size_t)lrow0 * (GK * 2);
        const size_t r1 = (size_t)lrow1 * (GK * 2);
        CP_ASYNC16(sbase + 0 * MATB + lrow0 * SROWB, gA0 + go + r0);
        CP_ASYNC16(sbase + 0 * MATB + lrow1 * SROWB, gA0 + go + r1);
        CP_ASYNC16(sbase + 1 * MATB + lrow0 * SROWB, gA1 + go + r0);
        CP_ASYNC16(sbase + 1 * MATB + lrow1 * SROWB, gA1 + go + r1);
        CP_ASYNC16(sbase + 2 * MATB + lrow0 * SROWB, gB0 + go + r0);
        CP_ASYNC16(sbase + 2 * MATB + lrow1 * SROWB, gB0 + go + r1);
        CP_ASYNC16(sbase + 3 * MATB + lrow0 * SROWB, gB1 + go + r0);
        CP_ASYNC16(sbase + 3 * MATB + lrow1 * SROWB, gB1 + go + r1);
        CP_COMMIT();
    };

    issue_load(0, 0);

    for (int s = 0; s < NSTG; ++s) {
        if (s + 1 < NSTG) {
            issue_load(s + 1, (s + 1) & 1);
            CP_WAIT1();
        } else {
            CP_WAIT0();
        }
        __syncthreads();

        const uint32_t base = sb + (s & 1) * BUFB;
#pragma unroll
        for (int step = 0; step < 2; ++step) {
            const uint32_t ko = step * 32;          // 16 bf16 = 32 bytes
            uint32_t ah[4][4], al[4][4], bh[2][4], bl[2][4];
#pragma unroll
            for (int mt = 0; mt < 4; ++mt) {
                ldsm4(ah[mt], base + 0 * MATB + arow[mt] + ko);
                ldsm4(al[mt], base + 1 * MATB + arow[mt] + ko);
            }
#pragma unroll
            for (int nb = 0; nb < 2; ++nb) {
                ldsm4(bh[nb], base + 2 * MATB + brow[nb] + ko);
                ldsm4(bl[nb], base + 3 * MATB + brow[nb] + ko);
            }
#pragma unroll
            for (int mt = 0; mt < 4; ++mt)
#pragma unroll
                for (int n8 = 0; n8 < 4; ++n8) {
                    const int nb = n8 >> 1, off = (n8 & 1) * 2;
                    mma_bf16(acc[mt][n8], ah[mt], &bh[nb][off]);
                    mma_bf16(acc[mt][n8], ah[mt], &bl[nb][off]);
                    mma_bf16(acc[mt][n8], al[mt], &bh[nb][off]);
                }
        }
        __syncthreads();
    }

    // ---------------- epilogue ----------------
#pragma unroll
    for (int mt = 0; mt < 4; ++mt) {
#pragma unroll
        for (int n8 = 0; n8 < 4; ++n8) {
            const int gm0 = bm + wm * 64 + mt * 16 + (lane >> 2);
            const int gn  = bn + wn * 32 + n8 * 8 + (lane & 3) * 2;
            const float2 bv = *(const float2*)(bias + gn);
            float2 v0, v1;
            v0.x = acc[mt][n8][0] + bv.x; v0.y = acc[mt][n8][1] + bv.y;
            v1.x = acc[mt][n8][2] + bv.x; v1.y = acc[mt][n8][3] + bv.y;
            if (MODE == 0) {
                *(float2*)(C + (size_t)gm0 * Ndim + gn)       = v0;
                *(float2*)(C + (size_t)(gm0 + 8) * Ndim + gn) = v1;
            } else {
                const int which = bn >> 11;                  // 0=Q,1=K,2=V
                const int hh = (bn >> 7) & 15;
                const int dd = (gn & 127);
                float* tgt = (which == 0) ? g_q : (which == 1 ? g_k : g_v);
                const int b0 = gm0 >> 11, s0 = gm0 & 2047;
                *(float2*)(tgt + (((size_t)(b0 * NH + hh) * SEQ + s0) * HD) + dd) = v0;
                const int gm1 = gm0 + 8;
                const int b1 = gm1 >> 11, s1 = gm1 & 2047;
                *(float2*)(tgt + (((size_t)(b1 * NH + hh) * SEQ + s1) * HD) + dd) = v1;
            }
        }
    }
}

// =================================================================
// RoPE (exact per reference)
// =================================================================
__global__ void rope_kernel()
{
    __shared__ float rq[HD], rk[HD];
    const int row = blockIdx.x;
    const int s = row & (SEQ - 1);
    const int d = threadIdx.x;
    float* qp = g_q + (size_t)row * HD;
    float* kp = g_k + (size_t)row * HD;
    rq[d] = qp[d];
    rk[d] = kp[d];
    __syncthreads();

    const int i = d >> 1;
    const double ang = exp(-((double)(2 * i) / 2048.0) * 9.210340371976184);
    const double fr = (double)s * ang;
    const float c  = (float)cos(fr);
    const float sn = (float)sin(fr);

    float oq, ok;
    if (d < 64) {
        oq = c * rq[d] - sn * rq[2 * d + 1];
        ok = c * rk[d] - sn * rk[2 * d + 1];
    } else {
        const int j = d - 64;
        oq = c * rq[d] + sn * rq[2 * j];
        ok = c * rk[d] + sn * rk[2 * j];
    }
    qp[d] = oq;
    kp[d] = ok;
}

// =================================================================
// Flash attention (SIMT, unchanged from R1 — optimize next round)
// =================================================================
#define QK_STRIDE 68
#define V_STRIDE  132
#define P_STRIDE  68
#define ATTN_SMEM ((128 * QK_STRIDE * 2 + 64 * V_STRIDE + 64 * P_STRIDE + 256) * 4)

__global__ void __launch_bounds__(256)
attn_kernel(const int* __restrict__ mask)
{
    extern __shared__ float sm[];
    float* Qs   = sm;
    float* Ks   = Qs + 128 * QK_STRIDE;
    float* Vs   = Ks + 128 * QK_STRIDE;
    float* Ps   = Vs + 64 * V_STRIDE;
    float* marr = Ps + 64 * P_STRIDE;
    float* larr = marr + 64;
    float* scl  = larr + 64;
    float* mskv = scl + 64;

    const int tid = threadIdx.x;
    const int tx = tid & 15, ty = tid >> 4;
    const int q0 = blockIdx.x * 64;
    const int h = blockIdx.y, b = blockIdx.z;

    const float* qbase = g_q + ((size_t)(b * NH + h) * SEQ + q0) * HD;
    const float* kbase = g_k + ((size_t)(b * NH + h) * SEQ) * HD;
    const float* vbase = g_v + ((size_t)(b * NH + h) * SEQ) * HD;
    const float SCALE = 0.08838834764831845f;

#pragma unroll
    for (int r = 0; r < 8; ++r) {
        const int idx = tid + r * 256;
        const int m = idx >> 5;
        const int dsg = (idx & 31) << 2;
        float4 v = *(const float4*)(qbase + m * HD + dsg);
        Qs[(dsg + 0) * QK_STRIDE + m] = v.x * SCALE;
        Qs[(dsg + 1) * QK_STRIDE + m] = v.y * SCALE;
        Qs[(dsg + 2) * QK_STRIDE + m] = v.z * SCALE;
        Qs[(dsg + 3) * QK_STRIDE + m] = v.w * SCALE;
    }
    if (tid < 64) { marr[tid] = -INFINITY; larr[tid] = 0.f; }

    float acc[4][8];
#pragma unroll
    for (int i = 0; i < 4; ++i)
#pragma unroll
        for (int j = 0; j < 8; ++j) acc[i][j] = 0.f;

    for (int kt = 0; kt < SEQ / 64; ++kt) {
        __syncthreads();
        const float* kb = kbase + (size_t)kt * 64 * HD;
        const float* vb = vbase + (size_t)kt * 64 * HD;
#pragma unroll
        for (int r = 0; r < 8; ++r) {
            const int idx = tid + r * 256;
            const int m = idx >> 5;
            const int dsg = (idx & 31) << 2;
            float4 kv = *(const float4*)(kb + m * HD + dsg);
            Ks[(dsg + 0) * QK_STRIDE + m] = kv.x;
            Ks[(dsg + 1) * QK_STRIDE + m] = kv.y;
            Ks[(dsg + 2) * QK_STRIDE + m] = kv.z;
            Ks[(dsg + 3) * QK_STRIDE + m] = kv.w;
            float4 vv = *(const float4*)(vb + m * HD + dsg);
            *(float4*)(Vs + m * V_STRIDE + dsg) = vv;
        }
        if (tid < 64) mskv[tid] = (float)mask[b * SEQ + kt * 64 + tid];
        __syncthreads();

        float sa[4][4];
#pragma unroll
        for (int i = 0; i < 4; ++i)
#pragma unroll
            for (int j = 0; j < 4; ++j) sa[i][j] = 0.f;
#pragma unroll 4
        for (int d = 0; d < 128; ++d) {
            float4 a  = *(const float4*)(Qs + d * QK_STRIDE + ty * 4);
            float4 bb = *(const float4*)(Ks + d * QK_STRIDE + tx * 4);
            float av[4] = {a.x, a.y, a.z, a.w};
            float bv[4] = {bb.x, bb.y, bb.z, bb.w};
#pragma unroll
            for (int i = 0; i < 4; ++i)
#pragma unroll
                for (int j = 0; j < 4; ++j)
                    sa[i][j] += av[i] * bv[j];
        }

        float msk[4];
#pragma unroll
        for (int j = 0; j < 4; ++j) msk[j] = mskv[tx * 4 + j];
#pragma unroll
        for (int i = 0; i < 4; ++i) {
#pragma unroll
            for (int j = 0; j < 4; ++j)
                if (msk[j] == 0.f) sa[i][j] = -1e9f;
            float rm = fmaxf(fmaxf(sa[i][0], sa[i][1]), fmaxf(sa[i][2], sa[i][3]));
            rm = fmaxf(rm, __shfl_xor_sync(0xffffffffu, rm, 8, 16));
            rm = fmaxf(rm, __shfl_xor_sync(0xffffffffu, rm, 4, 16));
            rm = fmaxf(rm, __shfl_xor_sync(0xffffffffu, rm, 2, 16));
            rm = fmaxf(rm, __shfl_xor_sync(0xffffffffu, rm, 1, 16));
            const int rowi = ty * 4 + i;
            const float mo = marr[rowi];
            const float mn = fmaxf(mo, rm);
            float rs = 0.f;
#pragma unroll
            for (int j = 0; j < 4; ++j) {
                float p = __expf(sa[i][j] - mn);
                Ps[(tx * 4 + j) * P_STRIDE + rowi] = p;
                rs += p;
            }
            rs += __shfl_xor_sync(0xffffffffu, rs, 8, 16);
            rs += __shfl_xor_sync(0xffffffffu, rs, 4, 16);
            rs += __shfl_xor_sync(0xffffffffu, rs, 2, 16);
            rs += __shfl_xor_sync(0xffffffffu, rs, 1, 16);
            if (tx == 0) {
                const float sc = (mo == -INFINITY) ? 0.f : __expf(mo - mn);
                scl[rowi]  = sc;
                larr[rowi] = larr[rowi] * sc + rs;
                marr[rowi] = mn;
            }
        }
        __syncthreads();

        float sc[4];
#pragma unroll
        for (int i = 0; i < 4; ++i) sc[i] = scl[ty * 4 + i];
#pragma unroll
        for (int i = 0; i < 4; ++i)
#pragma unroll
            for (int j = 0; j < 8; ++j) acc[i][j] *= sc[i];

#pragma unroll 4
        for (int k = 0; k < 64; ++k) {
            float4 a  = *(const float4*)(Ps + k * P_STRIDE + ty * 4);
            float4 b0 = *(const float4*)(Vs + k * V_STRIDE + tx * 4);
            float4 b1 = *(const float4*)(Vs + k * V_STRIDE + 64 + tx * 4);
            float av[4] = {a.x, a.y, a.z, a.w};
            float bv[8] = {b0.x, b0.y, b0.z, b0.w, b1.x, b1.y, b1.z, b1.w};
#pragma unroll
            for (int i = 0; i < 4; ++i)
#pragma unroll
                for (int j = 0; j < 8; ++j)
                    acc[i][j] += av[i] * bv[j];
        }
    }

#pragma unroll
    for (int i = 0; i < 4; ++i) {
        const float inv = 1.f / larr[ty * 4 + i];
        const int qrow = q0 + ty * 4 + i;
        float* obase = g_attn + ((size_t)b * SEQ + qrow) * EMB + h * HD;
        float4 v0, v1;
        v0.x = acc[i][0] * inv; v0.y = acc[i][1] * inv;
        v0.z = acc[i][2] * inv; v0.w = acc[i][3] * inv;
        v1.x = acc[i][4] * inv; v1.y = acc[i][5] * inv;
        v1.z = acc[i][6] * inv; v1.w = acc[i][7] * inv;
        *(float4*)(obase + tx * 4) = v0;
        *(float4*)(obase + 64 + tx * 4) = v1;
    }
}

// =================================================================
extern "C" void kernel_launch(void* const* d_in, const int* in_sizes, int n_in,
                              void* d_out, int out_size)
{
    const float* X    = (const float*)d_in[0];
    const int*   mask = (const int*)d_in[1];
    const float* Wqkv = (const float*)d_in[2];
    const float* bqkv = (const float*)d_in[3];
    const float* Wo   = (const float*)d_in[4];
    const float* bo   = (const float*)d_in[5];
    float* out = (float*)d_out;

    float* dAttn = nullptr;
    cudaGetSymbolAddress((void**)&dAttn, g_attn);
    __nv_bfloat16 *ahi, *alo, *w1hi, *w1lo, *w2hi, *w2lo;
    cudaGetSymbolAddress((void**)&ahi,  g_ahi);
    cudaGetSymbolAddress((void**)&alo,  g_alo);
    cudaGetSymbolAddress((void**)&w1hi, g_w1hi);
    cudaGetSymbolAddress((void**)&w1lo, g_w1lo);
    cudaGetSymbolAddress((void**)&w2hi, g_w2hi);
    cudaGetSymbolAddress((void**)&w2lo, g_w2lo);

    cudaFuncSetAttribute(gemm_mma<0>, cudaFuncAttributeMaxDynamicSharedMemorySize, GEMM_SMEM);
    cudaFuncSetAttribute(gemm_mma<1>, cudaFuncAttributeMaxDynamicSharedMemorySize, GEMM_SMEM);
    cudaFuncSetAttribute(attn_kernel, cudaFuncAttributeMaxDynamicSharedMemorySize, ATTN_SMEM);

    // 1) split-convert X and Wqkv to bf16 hi/lo
    cvt_split<<<(MROWS * GK) / 1024, 256>>>(X, ahi, alo, MROWS * GK);
    cvt_split<<<(NQKV * GK) / 1024, 256>>>(Wqkv, w1hi, w1lo, NQKV * GK);

    // 2) QKV projection (HMMA bf16x3) + scatter to [b,h,s,d]
    gemm_mma<1><<<dim3(NQKV / 128, MROWS / 128), 256, GEMM_SMEM>>>(
        ahi, alo, w1hi, w1lo, bqkv, nullptr, NQKV);

    // 3) RoPE in-place on Q and K
    rope_kernel<<<BATCH * NH * SEQ, 128>>>();

    // 4) flash attention (SIMT)
    attn_kernel<<<dim3(SEQ / 64, NH, BATCH), 256, ATTN_SMEM>>>(mask);

    // 5) split-convert attention output and Wo, then output projection
    cvt_split<<<(MROWS * EMB) / 1024, 256>>>(dAttn, ahi, alo, MROWS * EMB);
    cvt_split<<<(EMB * GK) / 1024, 256>>>(Wo, w2hi, w2lo, EMB * GK);
    gemm_mma<0><<<dim3(EMB / 128, MROWS / 128), 256, GEMM_SMEM>>>(
        ahi, alo, w2hi, w2lo, bo, out, EMB);
}

// round 9
// speedup vs baseline: 5.0820x; 2.2814x over previous
#include <cuda_runtime.h>
#include <cuda_bf16.h>
#include <math.h>
#include <stdint.h>

#define BATCH 2
#define SEQ   2048
#define EMB   2048
#define NH    16
#define HD    128
#define NQKV  6144
#define MROWS 4096
#define GK    2048
#define NSTG  (GK / 32)     // 64 stages of BK=32

// ---------------- scratch (no allocation allowed) ----------------
__device__ float g_q[BATCH * NH * SEQ * HD];     // fp32 Q pre-rope
__device__ float g_k[BATCH * NH * SEQ * HD];     // fp32 K pre-rope

__device__ __nv_bfloat16 g_qhi[BATCH * NH * SEQ * HD];
__device__ __nv_bfloat16 g_qlo[BATCH * NH * SEQ * HD];
__device__ __nv_bfloat16 g_khi[BATCH * NH * SEQ * HD];
__device__ __nv_bfloat16 g_klo[BATCH * NH * SEQ * HD];
__device__ __nv_bfloat16 g_vhi[BATCH * NH * SEQ * HD];
__device__ __nv_bfloat16 g_vlo[BATCH * NH * SEQ * HD];

__device__ __nv_bfloat16 g_ahi[MROWS * GK];     // X hi, later attn-out hi
__device__ __nv_bfloat16 g_alo[MROWS * GK];
__device__ __nv_bfloat16 g_w1hi[NQKV * GK];
__device__ __nv_bfloat16 g_w1lo[NQKV * GK];
__device__ __nv_bfloat16 g_w2hi[EMB * GK];
__device__ __nv_bfloat16 g_w2lo[EMB * GK];

__device__ float g_cs[SEQ * HD];
__device__ float g_sn[SEQ * HD];

// ================= family-generic PTX helpers ====================
__device__ __forceinline__ uint32_t smem_u32(const void* p) {
    uint32_t a;
    asm("{ .reg .u64 t; cvta.to.shared.u64 t, %1; cvt.u32.u64 %0, t; }" : "=r"(a) : "l"(p));
    return a;
}
#define CP_ASYNC16(s, g) \
    asm volatile("cp.async.cg.shared.global [%0], [%1], 16;" :: "r"(s), "l"(g))
#define CP_COMMIT() asm volatile("cp.async.commit_group;" ::: "memory")
#define CP_WAIT1()  asm volatile("cp.async.wait_group 1;" ::: "memory")
#define CP_WAIT0()  asm volatile("cp.async.wait_group 0;" ::: "memory")

__device__ __forceinline__ void ldsm4(uint32_t* r, uint32_t addr) {
    asm volatile("ldmatrix.sync.aligned.m8n8.x4.shared.b16 {%0,%1,%2,%3}, [%4];"
        : "=r"(r[0]), "=r"(r[1]), "=r"(r[2]), "=r"(r[3]) : "r"(addr));
}
__device__ __forceinline__ void ldsm4t(uint32_t* r, uint32_t addr) {
    asm volatile("ldmatrix.sync.aligned.m8n8.x4.trans.shared.b16 {%0,%1,%2,%3}, [%4];"
        : "=r"(r[0]), "=r"(r[1]), "=r"(r[2]), "=r"(r[3]) : "r"(addr));
}
__device__ __forceinline__ void mma_bf16(float* c, const uint32_t* a, const uint32_t* b) {
    asm volatile(
        "mma.sync.aligned.m16n8k16.row.col.f32.bf16.bf16.f32 "
        "{%0,%1,%2,%3}, {%4,%5,%6,%7}, {%8,%9}, {%0,%1,%2,%3};"
        : "+f"(c[0]), "+f"(c[1]), "+f"(c[2]), "+f"(c[3])
        : "r"(a[0]), "r"(a[1]), "r"(a[2]), "r"(a[3]), "r"(b[0]), "r"(b[1]));
}
__device__ __forceinline__ uint32_t packbf(float a, float b) {
    __nv_bfloat162 t;
    t.x = __float2bfloat16(a);
    t.y = __float2bfloat16(b);
    return *reinterpret_cast<uint32_t*>(&t);
}

// ================= fp32 -> bf16 hi/lo split ======================
__global__ void cvt_split(const float* __restrict__ x,
                          __nv_bfloat16* __restrict__ hi,
                          __nv_bfloat16* __restrict__ lo, int n)
{
    int i = (blockIdx.x * blockDim.x + threadIdx.x) * 4;
    if (i >= n) return;
    float4 v = *(const float4*)(x + i);
    __nv_bfloat16 h0 = __float2bfloat16(v.x);
    __nv_bfloat16 h1 = __float2bfloat16(v.y);
    __nv_bfloat16 h2 = __float2bfloat16(v.z);
    __nv_bfloat16 h3 = __float2bfloat16(v.w);
    __nv_bfloat16 l0 = __float2bfloat16(v.x - __bfloat162float(h0));
    __nv_bfloat16 l1 = __float2bfloat16(v.y - __bfloat162float(h1));
    __nv_bfloat16 l2 = __float2bfloat16(v.z - __bfloat162float(h2));
    __nv_bfloat16 l3 = __float2bfloat16(v.w - __bfloat162float(h3));
    __nv_bfloat162 a, b, c, d;
    a.x = h0; a.y = h1; b.x = h2; b.y = h3;
    c.x = l0; c.y = l1; d.x = l2; d.y = l3;
    *(__nv_bfloat162*)(hi + i)     = a;
    *(__nv_bfloat162*)(hi + i + 2) = b;
    *(__nv_bfloat162*)(lo + i)     = c;
    *(__nv_bfloat162*)(lo + i + 2) = d;
}

// =================================================================
// mma.sync bf16x3 GEMM (unchanged structure from R7; V path writes
// bf16 hi/lo directly).
// =================================================================
#define SROWB 80
#define MATB  (128 * SROWB)
#define BUFB  (4 * MATB)
#define GEMM_SMEM (2 * BUFB)

template <int MODE>
__global__ void __launch_bounds__(256, 1)
gemm_mma(const __nv_bfloat16* __restrict__ Ahi, const __nv_bfloat16* __restrict__ Alo,
         const __nv_bfloat16* __restrict__ Bhi, const __nv_bfloat16* __restrict__ Blo,
         const float* __restrict__ bias, float* __restrict__ C, int Ndim)
{
    extern __shared__ char smem[];
    const uint32_t sb = smem_u32(smem);
    const int tid = threadIdx.x;
    const int lane = tid & 31, wid = tid >> 5;
    const int wm = wid >> 2, wn = wid & 3;
    const int bm = blockIdx.y * 128, bn = blockIdx.x * 128;

    const char* gA0 = (const char*)(Ahi + (size_t)bm * GK);
    const char* gA1 = (const char*)(Alo + (size_t)bm * GK);
    const char* gB0 = (const char*)(Bhi + (size_t)bn * GK);
    const char* gB1 = (const char*)(Blo + (size_t)bn * GK);

    const int lrow0 = tid >> 2;
    const int lrow1 = 64 + (tid >> 2);
    const int lseg  = (tid & 3) * 16;

    uint32_t arow[4];
#pragma unroll
    for (int mt = 0; mt < 4; ++mt)
        arow[mt] = (uint32_t)((wm * 64 + mt * 16 + (lane & 15)) * SROWB + ((lane >> 4) << 4));
    uint32_t brow[2];
#pragma unroll
    for (int nb = 0; nb < 2; ++nb)
        brow[nb] = (uint32_t)((wn * 32 + nb * 16 + ((lane >> 4) << 3) + (lane & 7)) * SROWB
                              + (((lane >> 3) & 1) << 4));

    float acc[4][4][4];
#pragma unroll
    for (int i = 0; i < 4; ++i)
#pragma unroll
        for (int j = 0; j < 4; ++j)
#pragma unroll
            for (int k = 0; k < 4; ++k) acc[i][j][k] = 0.f;

    auto issue_load = [&](int stage, int buf) {
        const size_t kb = (size_t)stage * 64;
        const uint32_t sbase = sb + buf * BUFB + lseg;
        const size_t go = kb + lseg;
        const size_t r0 = (size_t)lrow0 * (GK * 2);
        const size_t r1 = (size_t)lrow1 * (GK * 2);
        CP_ASYNC16(sbase + 0 * MATB + lrow0 * SROWB, gA0 + go + r0);
        CP_ASYNC16(sbase + 0 * MATB + lrow1 * SROWB, gA0 + go + r1);
        CP_ASYNC16(sbase + 1 * MATB + lrow0 * SROWB, gA1 + go + r0);
        CP_ASYNC16(sbase + 1 * MATB + lrow1 * SROWB, gA1 + go + r1);
        CP_ASYNC16(sbase + 2 * MATB + lrow0 * SROWB, gB0 + go + r0);
        CP_ASYNC16(sbase + 2 * MATB + lrow1 * SROWB, gB0 + go + r1);
        CP_ASYNC16(sbase + 3 * MATB + lrow0 * SROWB, gB1 + go + r0);
        CP_ASYNC16(sbase + 3 * MATB + lrow1 * SROWB, gB1 + go + r1);
        CP_COMMIT();
    };

    issue_load(0, 0);

    for (int s = 0; s < NSTG; ++s) {
        if (s + 1 < NSTG) {
            issue_load(s + 1, (s + 1) & 1);
            CP_WAIT1();
        } else {
            CP_WAIT0();
        }
        __syncthreads();

        const uint32_t base = sb + (s & 1) * BUFB;
#pragma unroll
        for (int step = 0; step < 2; ++step) {
            const uint32_t ko = step * 32;
            uint32_t ah[4][4], al[4][4], bh[2][4], bl[2][4];
#pragma unroll
            for (int mt = 0; mt < 4; ++mt) {
                ldsm4(ah[mt], base + 0 * MATB + arow[mt] + ko);
                ldsm4(al[mt], base + 1 * MATB + arow[mt] + ko);
            }
#pragma unroll
            for (int nb = 0; nb < 2; ++nb) {
                ldsm4(bh[nb], base + 2 * MATB + brow[nb] + ko);
                ldsm4(bl[nb], base + 3 * MATB + brow[nb] + ko);
            }
#pragma unroll
            for (int mt = 0; mt < 4; ++mt)
#pragma unroll
                for (int n8 = 0; n8 < 4; ++n8) {
                    const int nb = n8 >> 1, off = (n8 & 1) * 2;
                    mma_bf16(acc[mt][n8], ah[mt], &bh[nb][off]);
                    mma_bf16(acc[mt][n8], ah[mt], &bl[nb][off]);
                    mma_bf16(acc[mt][n8], al[mt], &bh[nb][off]);
                }
        }
        __syncthreads();
    }

    // ---------------- epilogue ----------------
#pragma unroll
    for (int mt = 0; mt < 4; ++mt) {
#pragma unroll
        for (int n8 = 0; n8 < 4; ++n8) {
            const int gm0 = bm + wm * 64 + mt * 16 + (lane >> 2);
            const int gn  = bn + wn * 32 + n8 * 8 + (lane & 3) * 2;
            const float2 bv = *(const float2*)(bias + gn);
            float2 v0, v1;
            v0.x = acc[mt][n8][0] + bv.x; v0.y = acc[mt][n8][1] + bv.y;
            v1.x = acc[mt][n8][2] + bv.x; v1.y = acc[mt][n8][3] + bv.y;
            if (MODE == 0) {
                *(float2*)(C + (size_t)gm0 * Ndim + gn)       = v0;
                *(float2*)(C + (size_t)(gm0 + 8) * Ndim + gn) = v1;
            } else {
                const int which = bn >> 11;                  // 0=Q,1=K,2=V
                const int hh = (bn >> 7) & 15;
                const int dd = (gn & 127);
                const int b0 = gm0 >> 11, s0 = gm0 & 2047;
                const int gm1 = gm0 + 8;
                const int b1 = gm1 >> 11, s1 = gm1 & 2047;
                const size_t o0 = (((size_t)(b0 * NH + hh) * SEQ + s0) * HD) + dd;
                const size_t o1 = (((size_t)(b1 * NH + hh) * SEQ + s1) * HD) + dd;
                if (which == 2) {
                    // split to bf16 hi/lo directly
                    float h0 = __bfloat162float(__float2bfloat16(v0.x));
                    float h1 = __bfloat162float(__float2bfloat16(v0.y));
                    float h2 = __bfloat162float(__float2bfloat16(v1.x));
                    float h3 = __bfloat162float(__float2bfloat16(v1.y));
                    *(uint32_t*)(g_vhi + o0) = packbf(v0.x, v0.y);
                    *(uint32_t*)(g_vlo + o0) = packbf(v0.x - h0, v0.y - h1);
                    *(uint32_t*)(g_vhi + o1) = packbf(v1.x, v1.y);
                    *(uint32_t*)(g_vlo + o1) = packbf(v1.x - h2, v1.y - h3);
                } else {
                    float* tgt = (which == 0) ? g_q : g_k;
                    *(float2*)(tgt + o0) = v0;
                    *(float2*)(tgt + o1) = v1;
                }
            }
        }
    }
}

// =================================================================
// RoPE: table once (double precision), then fp32 apply + bf16 split.
// =================================================================
__global__ void rope_table()
{
    const int s = blockIdx.x, d = threadIdx.x;
    const int i = d >> 1;
    const double ang = exp(-((double)(2 * i) / 2048.0) * 9.210340371976184);
    const double fr = (double)s * ang;
    g_cs[s * HD + d] = (float)cos(fr);
    g_sn[s * HD + d] = (float)sin(fr);
}

__global__ void rope_apply()
{
    __shared__ float rq[HD], rk[HD];
    const int row = blockIdx.x;            // (b*NH+h)*SEQ + s
    const int s = row & (SEQ - 1);
    const int d = threadIdx.x;
    rq[d] = g_q[(size_t)row * HD + d];
    rk[d] = g_k[(size_t)row * HD + d];
    __syncthreads();

    const float c  = g_cs[s * HD + d];
    const float sn = g_sn[s * HD + d];
    float oq, ok;
    if (d < 64) {
        oq = c * rq[d] - sn * rq[2 * d + 1];
        ok = c * rk[d] - sn * rk[2 * d + 1];
    } else {
        const int j = d - 64;
        oq = c * rq[d] + sn * rq[2 * j];
        ok = c * rk[d] + sn * rk[2 * j];
    }
    const float qs = oq * 0.08838834764831845f;   // fold 1/sqrt(HD)
    const size_t idx = (size_t)row * HD + d;
    __nv_bfloat16 qh = __float2bfloat16(qs);
    g_qhi[idx] = qh;
    g_qlo[idx] = __float2bfloat16(qs - __bfloat162float(qh));
    __nv_bfloat16 kh = __float2bfloat16(ok);
    g_khi[idx] = kh;
    g_klo[idx] = __float2bfloat16(ok - __bfloat162float(kh));
}

// =================================================================
// MMA flash attention, bf16x3.
// CTA: 128 q-rows, 8 warps x 16 rows, 32-key blocks, double-buffered
// K/V hi/lo via cp.async. P hi/lo staged in smem per warp. Output
// written directly as bf16 hi/lo (GEMM2 input).
// =================================================================
#define AKB   32
#define QROWB 272        // 128 bf16 padded to 136 (stride 272 B): conflict-free ldmatrix
#define PROWB 80         // 32 bf16 padded to 40 (stride 80 B)
#define KSTGB (AKB * QROWB)          // 8704
#define OFF_QHI 0
#define OFF_QLO 34816
#define OFF_KHI 69632
#define OFF_KLO (OFF_KHI + 2 * KSTGB)    // 87040
#define OFF_VHI (OFF_KLO + 2 * KSTGB)    // 104448
#define OFF_VLO (OFF_VHI + 2 * KSTGB)    // 121856
#define OFF_PHI (OFF_VLO + 2 * KSTGB)    // 139264
#define OFF_PLO (OFF_PHI + 128 * PROWB)  // 149504
#define OFF_MSK (OFF_PLO + 128 * PROWB)  // 159744
#define ATTN_SMEM (OFF_MSK + 128)        // 159872

__global__ void __launch_bounds__(256, 1)
attn_mma(const int* __restrict__ mask)
{
    extern __shared__ char smem[];
    const uint32_t sb = smem_u32(smem);
    const int tid = threadIdx.x;
    const int lane = tid & 31, wm = tid >> 5;
    const int q0 = blockIdx.x * 128;
    const int h = blockIdx.y, b = blockIdx.z;
    const size_t bh = ((size_t)b * NH + h) * SEQ;

    // ---- load Q tile (hi+lo), 128 rows x 256B ----
    {
        const char* gqh = (const char*)(g_qhi + (bh + q0) * HD);
        const char* gql = (const char*)(g_qlo + (bh + q0) * HD);
#pragma unroll
        for (int i = 0; i < 8; ++i) {
            const int c = tid + i * 256;
            const int row = c >> 4, seg = (c & 15) * 16;
            CP_ASYNC16(sb + OFF_QHI + row * QROWB + seg, gqh + (size_t)row * 256 + seg);
            CP_ASYNC16(sb + OFF_QLO + row * QROWB + seg, gql + (size_t)row * 256 + seg);
        }
        CP_COMMIT();
    }
    auto loadKV = [&](int kt) {
        const int st = kt & 1;
        const char* gkh = (const char*)(g_khi + (bh + kt * AKB) * HD);
        const char* gkl = (const char*)(g_klo + (bh + kt * AKB) * HD);
        const char* gvh = (const char*)(g_vhi + (bh + kt * AKB) * HD);
        const char* gvl = (const char*)(g_vlo + (bh + kt * AKB) * HD);
#pragma unroll
        for (int i = 0; i < 2; ++i) {
            const int c = tid + i * 256;          // 0..511
            const int row = c >> 4, seg = (c & 15) * 16;
            const uint32_t so = st * KSTGB + row * QROWB + seg;
            const size_t go = (size_t)row * 256 + seg;
            CP_ASYNC16(sb + OFF_KHI + so, gkh + go);
            CP_ASYNC16(sb + OFF_KLO + so, gkl + go);
            CP_ASYNC16(sb + OFF_VHI + so, gvh + go);
            CP_ASYNC16(sb + OFF_VLO + so, gvl + go);
        }
        CP_COMMIT();
    };
    loadKV(0);

    float o[16][4];
#pragma unroll
    for (int t = 0; t < 16; ++t)
#pragma unroll
        for (int j = 0; j < 4; ++j) o[t][j] = 0.f;
    float m0 = -INFINITY, m1 = -INFINITY, l0 = 0.f, l1 = 0.f;

    const int r0 = lane >> 2;                     // local row (and r0+8)
    const uint32_t qoff = (wm * 16 + (lane & 15)) * QROWB + ((lane >> 4) << 4);
    const uint32_t koff = ((lane & 15)) * QROWB + (((lane >> 3) & 1) << 4)
                        - (((lane >> 3) & 1) << 3) * QROWB;  // = ((lane&7)+((lane>>4)<<3))*QROWB + ((lane>>3)&1)*16
    // recompute cleanly:
    const uint32_t kfr = (((lane >> 4) << 3) + (lane & 7)) * QROWB + (((lane >> 3) & 1) << 4);
    const uint32_t poff = (wm * 16 + (lane & 15)) * PROWB + ((lane >> 4) << 4);
    const uint32_t vfr = (lane & 15) * QROWB + (((lane >> 4) << 3) << 1);  // row=(lane&15), col=(lane>>4)*8 bf16

    float* msk = (float*)(smem + OFF_MSK);

    for (int kt = 0; kt < SEQ / AKB; ++kt) {
        __syncthreads();
        if (kt + 1 < SEQ / AKB) loadKV(kt + 1);
        if (tid < AKB) msk[tid] = (float)mask[b * SEQ + kt * AKB + tid];
        if (kt + 1 < SEQ / AKB) { CP_WAIT1(); } else { CP_WAIT0(); }
        __syncthreads();

        const uint32_t kbh = sb + OFF_KHI + (kt & 1) * KSTGB;
        const uint32_t kbl = sb + OFF_KLO + (kt & 1) * KSTGB;

        // ---- S = Q K^T (bf16x3) ----
        float s[4][4];
#pragma unroll
        for (int t = 0; t < 4; ++t)
#pragma unroll
            for (int j = 0; j < 4; ++j) s[t][j] = 0.f;
#pragma unroll
        for (int ks = 0; ks < 8; ++ks) {
            uint32_t qh[4], ql[4], kh[2][4], kl[2][4];
            ldsm4(qh, sb + OFF_QHI + qoff + ks * 32);
            ldsm4(ql, sb + OFF_QLO + qoff + ks * 32);
#pragma unroll
            for (int nb = 0; nb < 2; ++nb) {
                ldsm4(kh[nb], kbh + nb * 16 * QROWB + kfr + ks * 32);
                ldsm4(kl[nb], kbl + nb * 16 * QROWB + kfr + ks * 32);
            }
#pragma unroll
            for (int t = 0; t < 4; ++t) {
                const int nb = t >> 1, off = (t & 1) * 2;
                mma_bf16(s[t], qh, &kh[nb][off]);
                mma_bf16(s[t], qh, &kl[nb][off]);
                mma_bf16(s[t], ql, &kh[nb][off]);
            }
        }

        // ---- online softmax (rows fully in-quad) ----
        float rm0 = -INFINITY, rm1 = -INFINITY;
#pragma unroll
        for (int t = 0; t < 4; ++t) {
            const int c = t * 8 + (lane & 3) * 2;
            const float k0 = msk[c], k1 = msk[c + 1];
            if (k0 == 0.f) { s[t][0] = -1e9f; s[t][2] = -1e9f; }
            if (k1 == 0.f) { s[t][1] = -1e9f; s[t][3] = -1e9f; }
            rm0 = fmaxf(rm0, fmaxf(s[t][0], s[t][1]));
            rm1 = fmaxf(rm1, fmaxf(s[t][2], s[t][3]));
        }
        rm0 = fmaxf(rm0, __shfl_xor_sync(0xffffffffu, rm0, 1));
        rm0 = fmaxf(rm0, __shfl_xor_sync(0xffffffffu, rm0, 2));
        rm1 = fmaxf(rm1, __shfl_xor_sync(0xffffffffu, rm1, 1));
        rm1 = fmaxf(rm1, __shfl_xor_sync(0xffffffffu, rm1, 2));
        const float mn0 = fmaxf(m0, rm0);
        const float mn1 = fmaxf(m1, rm1);
        const float sc0 = (m0 == -INFINITY) ? 0.f : __expf(m0 - mn0);
        const float sc1 = (m1 == -INFINITY) ? 0.f : __expf(m1 - mn1);

        float rs0 = 0.f, rs1 = 0.f;
#pragma unroll
        for (int t = 0; t < 4; ++t) {
            const int c = t * 8 + (lane & 3) * 2;
            const float e00 = __expf(s[t][0] - mn0);
            const float e01 = __expf(s[t][1] - mn0);
            const float e10 = __expf(s[t][2] - mn1);
            const float e11 = __expf(s[t][3] - mn1);
            rs0 += e00 + e01;
            rs1 += e10 + e11;
            const float h00 = __bfloat162float(__float2bfloat16(e00));
            const float h01 = __bfloat162float(__float2bfloat16(e01));
            const float h10 = __bfloat162float(__float2bfloat16(e10));
            const float h11 = __bfloat162float(__float2bfloat16(e11));
            char* p0 = smem + (wm * 16 + r0) * PROWB + c * 2;
            char* p1 = smem + (wm * 16 + r0 + 8) * PROWB + c * 2;
            *(uint32_t*)(p0 + OFF_PHI) = packbf(e00, e01);
            *(uint32_t*)(p0 + OFF_PLO) = packbf(e00 - h00, e01 - h01);
            *(uint32_t*)(p1 + OFF_PHI) = packbf(e10, e11);
            *(uint32_t*)(p1 + OFF_PLO) = packbf(e10 - h10, e11 - h11);
        }
        rs0 += __shfl_xor_sync(0xffffffffu, rs0, 1);
        rs0 += __shfl_xor_sync(0xffffffffu, rs0, 2);
        rs1 += __shfl_xor_sync(0xffffffffu, rs1, 1);
        rs1 += __shfl_xor_sync(0xffffffffu, rs1, 2);
        l0 = l0 * sc0 + rs0; m0 = mn0;
        l1 = l1 * sc1 + rs1; m1 = mn1;

#pragma unroll
        for (int t = 0; t < 16; ++t) {
            o[t][0] *= sc0; o[t][1] *= sc0;
            o[t][2] *= sc1; o[t][3] *= sc1;
        }
        __syncwarp();

        // ---- O += P V (bf16x3), V B-frags via ldmatrix.trans ----
        const uint32_t vbh = sb + OFF_VHI + (kt & 1) * KSTGB;
        const uint32_t vbl = sb + OFF_VLO + (kt & 1) * KSTGB;
#pragma unroll
        for (int ks = 0; ks < 2; ++ks) {
            uint32_t ph[4], pl[4];
            ldsm4(ph, sb + OFF_PHI + poff + ks * 32);
            ldsm4(pl, sb + OFF_PLO + poff + ks * 32);
#pragma unroll
            for (int nb = 0; nb < 8; ++nb) {
                uint32_t vh[4], vl[4];
                const uint32_t va = (ks * 16) * QROWB + vfr + nb * 32;
                ldsm4t(vh, vbh + va);
                ldsm4t(vl, vbl + va);
#pragma unroll
                for (int half = 0; half < 2; ++half) {
                    const int t = nb * 2 + half;
                    const int off = half * 2;
                    mma_bf16(o[t], ph, &vh[off]);
                    mma_bf16(o[t], ph, &vl[off]);
                    mma_bf16(o[t], pl, &vh[off]);
                }
            }
        }
    }

    // ---- epilogue: normalize, split to bf16 hi/lo, store ----
    const float inv0 = 1.f / l0;
    const float inv1 = 1.f / l1;
    const size_t row0 = ((size_t)b * SEQ + q0 + wm * 16 + r0) * EMB + h * HD;
    const size_t row1 = row0 + (size_t)8 * EMB;
#pragma unroll
    for (int t = 0; t < 16; ++t) {
        const int c = t * 8 + (lane & 3) * 2;
        const float v0 = o[t][0] * inv0, v1 = o[t][1] * inv0;
        const float v2 = o[t][2] * inv1, v3 = o[t][3] * inv1;
        const float h0 = __bfloat162float(__float2bfloat16(v0));
        const float h1 = __bfloat162float(__float2bfloat16(v1));
        const float h2 = __bfloat162float(__float2bfloat16(v2));
        const float h3 = __bfloat162float(__float2bfloat16(v3));
        *(uint32_t*)(g_ahi + row0 + c) = packbf(v0, v1);
        *(uint32_t*)(g_alo + row0 + c) = packbf(v0 - h0, v1 - h1);
        *(uint32_t*)(g_ahi + row1 + c) = packbf(v2, v3);
        *(uint32_t*)(g_alo + row1 + c) = packbf(v2 - h2, v3 - h3);
    }
}

// =================================================================
extern "C" void kernel_launch(void* const* d_in, const int* in_sizes, int n_in,
                              void* d_out, int out_size)
{
    const float* X    = (const float*)d_in[0];
    const int*   mask = (const int*)d_in[1];
    const float* Wqkv = (const float*)d_in[2];
    const float* bqkv = (const float*)d_in[3];
    const float* Wo   = (const float*)d_in[4];
    const float* bo   = (const float*)d_in[5];
    float* out = (float*)d_out;

    __nv_bfloat16 *ahi, *alo, *w1hi, *w1lo, *w2hi, *w2lo;
    cudaGetSymbolAddress((void**)&ahi,  g_ahi);
    cudaGetSymbolAddress((void**)&alo,  g_alo);
    cudaGetSymbolAddress((void**)&w1hi, g_w1hi);
    cudaGetSymbolAddress((void**)&w1lo, g_w1lo);
    cudaGetSymbolAddress((void**)&w2hi, g_w2hi);
    cudaGetSymbolAddress((void**)&w2lo, g_w2lo);

    cudaFuncSetAttribute(gemm_mma<0>, cudaFuncAttributeMaxDynamicSharedMemorySize, GEMM_SMEM);
    cudaFuncSetAttribute(gemm_mma<1>, cudaFuncAttributeMaxDynamicSharedMemorySize, GEMM_SMEM);
    cudaFuncSetAttribute(attn_mma, cudaFuncAttributeMaxDynamicSharedMemorySize, ATTN_SMEM);

    // 1) conversions + rope table
    cvt_split<<<(MROWS * GK) / 1024, 256>>>(X, ahi, alo, MROWS * GK);
    cvt_split<<<(NQKV * GK) / 1024, 256>>>(Wqkv, w1hi, w1lo, NQKV * GK);
    cvt_split<<<(EMB * GK) / 1024, 256>>>(Wo, w2hi, w2lo, EMB * GK);
    rope_table<<<SEQ, HD>>>();

    // 2) QKV projection (HMMA bf16x3); Q,K -> fp32, V -> bf16 hi/lo
    gemm_mma<1><<<dim3(NQKV / 128, MROWS / 128), 256, GEMM_SMEM>>>(
        ahi, alo, w1hi, w1lo, bqkv, nullptr, NQKV);

    // 3) RoPE + Q-scale + bf16 split
    rope_apply<<<BATCH * NH * SEQ, HD>>>();

    // 4) MMA flash attention -> writes g_ahi/g_alo directly
    attn_mma<<<dim3(SEQ / 128, NH, BATCH), 256, ATTN_SMEM>>>(mask);

    // 5) output projection
    gemm_mma<0><<<dim3(EMB / 128, MROWS / 128), 256, GEMM_SMEM>>>(
        ahi, alo, w2hi, w2lo, bo, out, EMB);
}

// round 10
// speedup vs baseline: 5.2118x; 1.0256x over previous
#include <cuda_runtime.h>
#include <cuda_bf16.h>
#include <math.h>
#include <stdint.h>

#define BATCH 2
#define SEQ   2048
#define EMB   2048
#define NH    16
#define HD    128
#define NQKV  6144
#define MROWS 4096
#define GK    2048
#define NSTG  (GK / 32)     // 64 stages of BK=32

// ---------------- scratch (no allocation allowed) ----------------
__device__ float g_q[BATCH * NH * SEQ * HD];     // fp32 Q pre-rope
__device__ float g_k[BATCH * NH * SEQ * HD];     // fp32 K pre-rope

__device__ __nv_bfloat16 g_qhi[BATCH * NH * SEQ * HD];
__device__ __nv_bfloat16 g_qlo[BATCH * NH * SEQ * HD];
__device__ __nv_bfloat16 g_khi[BATCH * NH * SEQ * HD];
__device__ __nv_bfloat16 g_klo[BATCH * NH * SEQ * HD];
__device__ __nv_bfloat16 g_vhi[BATCH * NH * SEQ * HD];
__device__ __nv_bfloat16 g_vlo[BATCH * NH * SEQ * HD];

__device__ __nv_bfloat16 g_ahi[MROWS * GK];     // X hi, later attn-out hi
__device__ __nv_bfloat16 g_alo[MROWS * GK];
__device__ __nv_bfloat16 g_w1hi[NQKV * GK];
__device__ __nv_bfloat16 g_w1lo[NQKV * GK];
__device__ __nv_bfloat16 g_w2hi[EMB * GK];
__device__ __nv_bfloat16 g_w2lo[EMB * GK];

__device__ float g_cs[SEQ * HD];
__device__ float g_sn[SEQ * HD];

// ================= family-generic PTX helpers ====================
__device__ __forceinline__ uint32_t smem_u32(const void* p) {
    uint32_t a;
    asm("{ .reg .u64 t; cvta.to.shared.u64 t, %1; cvt.u32.u64 %0, t; }" : "=r"(a) : "l"(p));
    return a;
}
#define CP_ASYNC16(s, g) \
    asm volatile("cp.async.cg.shared.global [%0], [%1], 16;" :: "r"(s), "l"(g))
#define CP_COMMIT() asm volatile("cp.async.commit_group;" ::: "memory")
#define CP_WAIT1()  asm volatile("cp.async.wait_group 1;" ::: "memory")
#define CP_WAIT0()  asm volatile("cp.async.wait_group 0;" ::: "memory")

__device__ __forceinline__ void ldsm4(uint32_t* r, uint32_t addr) {
    asm volatile("ldmatrix.sync.aligned.m8n8.x4.shared.b16 {%0,%1,%2,%3}, [%4];"
        : "=r"(r[0]), "=r"(r[1]), "=r"(r[2]), "=r"(r[3]) : "r"(addr));
}
__device__ __forceinline__ void ldsm4t(uint32_t* r, uint32_t addr) {
    asm volatile("ldmatrix.sync.aligned.m8n8.x4.trans.shared.b16 {%0,%1,%2,%3}, [%4];"
        : "=r"(r[0]), "=r"(r[1]), "=r"(r[2]), "=r"(r[3]) : "r"(addr));
}
__device__ __forceinline__ void mma_bf16(float* c, const uint32_t* a, const uint32_t* b) {
    asm volatile(
        "mma.sync.aligned.m16n8k16.row.col.f32.bf16.bf16.f32 "
        "{%0,%1,%2,%3}, {%4,%5,%6,%7}, {%8,%9}, {%0,%1,%2,%3};"
        : "+f"(c[0]), "+f"(c[1]), "+f"(c[2]), "+f"(c[3])
        : "r"(a[0]), "r"(a[1]), "r"(a[2]), "r"(a[3]), "r"(b[0]), "r"(b[1]));
}
__device__ __forceinline__ uint32_t packbf(float a, float b) {
    __nv_bfloat162 t;
    t.x = __float2bfloat16(a);
    t.y = __float2bfloat16(b);
    return *reinterpret_cast<uint32_t*>(&t);
}

// ================= fp32 -> bf16 hi/lo split ======================
__global__ void cvt_split(const float* __restrict__ x,
                          __nv_bfloat16* __restrict__ hi,
                          __nv_bfloat16* __restrict__ lo, int n)
{
    int i = (blockIdx.x * blockDim.x + threadIdx.x) * 4;
    if (i >= n) return;
    float4 v = *(const float4*)(x + i);
    __nv_bfloat16 h0 = __float2bfloat16(v.x);
    __nv_bfloat16 h1 = __float2bfloat16(v.y);
    __nv_bfloat16 h2 = __float2bfloat16(v.z);
    __nv_bfloat16 h3 = __float2bfloat16(v.w);
    __nv_bfloat16 l0 = __float2bfloat16(v.x - __bfloat162float(h0));
    __nv_bfloat16 l1 = __float2bfloat16(v.y - __bfloat162float(h1));
    __nv_bfloat16 l2 = __float2bfloat16(v.z - __bfloat162float(h2));
    __nv_bfloat16 l3 = __float2bfloat16(v.w - __bfloat162float(h3));
    __nv_bfloat162 a, b, c, d;
    a.x = h0; a.y = h1; b.x = h2; b.y = h3;
    c.x = l0; c.y = l1; d.x = l2; d.y = l3;
    *(__nv_bfloat162*)(hi + i)     = a;
    *(__nv_bfloat162*)(hi + i + 2) = b;
    *(__nv_bfloat162*)(lo + i)     = c;
    *(__nv_bfloat162*)(lo + i + 2) = d;
}

// =================================================================
// mma.sync bf16x3 GEMM: C[M,N] = A[M,K] @ B[N,K]^T + bias
// CTA tile 128x256, 8 warps (2x4) of 64x64, BK=32, double-buffered
// cp.async. ldsm:MMA ratio 16:96 per warp k-step (tensor-bound).
// MODE 0: row-major C     MODE 1: scatter Q/K fp32, V bf16 hi/lo
// =================================================================
#define SROWB 80                  // bytes per smem row (64 data + 16 pad)
#define ATILE (128 * SROWB)       // 10240
#define BTILE (256 * SROWB)       // 20480
#define STAGEB (2 * ATILE + 2 * BTILE)   // 61440
#define GEMM_SMEM (2 * STAGEB)           // 122880

template <int MODE>
__global__ void __launch_bounds__(256, 1)
gemm_mma(const __nv_bfloat16* __restrict__ Ahi, const __nv_bfloat16* __restrict__ Alo,
         const __nv_bfloat16* __restrict__ Bhi, const __nv_bfloat16* __restrict__ Blo,
         const float* __restrict__ bias, float* __restrict__ C, int Ndim)
{
    extern __shared__ char smem[];
    const uint32_t sb = smem_u32(smem);
    const int tid = threadIdx.x;
    const int lane = tid & 31, wid = tid >> 5;
    const int wm = wid >> 2, wn = wid & 3;          // 2 x 4 warp grid
    const int bm = blockIdx.y * 128, bn = blockIdx.x * 256;

    const char* gA0 = (const char*)(Ahi + (size_t)bm * GK);
    const char* gA1 = (const char*)(Alo + (size_t)bm * GK);
    const char* gB0 = (const char*)(Bhi + (size_t)bn * GK);
    const char* gB1 = (const char*)(Blo + (size_t)bn * GK);

    // ldmatrix fragment offsets
    uint32_t arow[4];
#pragma unroll
    for (int mt = 0; mt < 4; ++mt)
        arow[mt] = (uint32_t)((wm * 64 + mt * 16 + (lane & 15)) * SROWB + ((lane >> 4) << 4));
    uint32_t brow[4];
#pragma unroll
    for (int nb = 0; nb < 4; ++nb)
        brow[nb] = (uint32_t)((wn * 64 + nb * 16 + ((lane >> 4) << 3) + (lane & 7)) * SROWB
                              + (((lane >> 3) & 1) << 4));

    float acc[4][8][4];
#pragma unroll
    for (int i = 0; i < 4; ++i)
#pragma unroll
        for (int j = 0; j < 8; ++j)
#pragma unroll
            for (int k = 0; k < 4; ++k) acc[i][j][k] = 0.f;

    auto issue_load = [&](int stage, int buf) {
        const size_t kb = (size_t)stage * 64;        // BK=32 bf16 = 64 B
        const uint32_t base = sb + buf * STAGEB;
#pragma unroll
        for (int r = 0; r < 2; ++r) {                // A: 128 rows x 4 chunks
            const int idx = tid + r * 256;
            const int row = idx >> 2;
            const int seg = (idx & 3) * 16;
            const size_t go = (size_t)row * (GK * 2) + kb + seg;
            const uint32_t so = row * SROWB + seg;
            CP_ASYNC16(base + 0     + so, gA0 + go);
            CP_ASYNC16(base + ATILE + so, gA1 + go);
        }
#pragma unroll
        for (int r = 0; r < 4; ++r) {                // B: 256 rows x 4 chunks
            const int idx = tid + r * 256;
            const int row = idx >> 2;
            const int seg = (idx & 3) * 16;
            const size_t go = (size_t)row * (GK * 2) + kb + seg;
            const uint32_t so = row * SROWB + seg;
            CP_ASYNC16(base + 2 * ATILE         + so, gB0 + go);
            CP_ASYNC16(base + 2 * ATILE + BTILE + so, gB1 + go);
        }
        CP_COMMIT();
    };

    issue_load(0, 0);

    for (int s = 0; s < NSTG; ++s) {
        if (s + 1 < NSTG) {
            issue_load(s + 1, (s + 1) & 1);
            CP_WAIT1();
        } else {
            CP_WAIT0();
        }
        __syncthreads();

        const uint32_t base = sb + (s & 1) * STAGEB;
        const uint32_t abase = base;
        const uint32_t bbase = base + 2 * ATILE;
#pragma unroll
        for (int step = 0; step < 2; ++step) {
            const uint32_t ko = step * 32;           // 16 bf16 = 32 B
            uint32_t bh[4][4], bl[4][4];
#pragma unroll
            for (int nb = 0; nb < 4; ++nb) {
                ldsm4(bh[nb], bbase + brow[nb] + ko);
                ldsm4(bl[nb], bbase + BTILE + brow[nb] + ko);
            }
#pragma unroll
            for (int mt = 0; mt < 4; ++mt) {
                uint32_t ah[4], al[4];
                ldsm4(ah, abase + arow[mt] + ko);
                ldsm4(al, abase + ATILE + arow[mt] + ko);
#pragma unroll
                for (int n8 = 0; n8 < 8; ++n8) {
                    const int nb = n8 >> 1, off = (n8 & 1) * 2;
                    mma_bf16(acc[mt][n8], ah, &bh[nb][off]);
                    mma_bf16(acc[mt][n8], ah, &bl[nb][off]);
                    mma_bf16(acc[mt][n8], al, &bh[nb][off]);
                }
            }
        }
        __syncthreads();
    }

    // ---------------- epilogue ----------------
#pragma unroll
    for (int mt = 0; mt < 4; ++mt) {
#pragma unroll
        for (int n8 = 0; n8 < 8; ++n8) {
            const int gm0 = bm + wm * 64 + mt * 16 + (lane >> 2);
            const int gn  = bn + wn * 64 + n8 * 8 + (lane & 3) * 2;
            const float2 bv = *(const float2*)(bias + gn);
            float2 v0, v1;
            v0.x = acc[mt][n8][0] + bv.x; v0.y = acc[mt][n8][1] + bv.y;
            v1.x = acc[mt][n8][2] + bv.x; v1.y = acc[mt][n8][3] + bv.y;
            if (MODE == 0) {
                *(float2*)(C + (size_t)gm0 * Ndim + gn)       = v0;
                *(float2*)(C + (size_t)(gm0 + 8) * Ndim + gn) = v1;
            } else {
                const int which = gn >> 11;                  // 0=Q,1=K,2=V
                const int hh = (gn >> 7) & 15;
                const int dd = (gn & 127);
                const int b0 = gm0 >> 11, s0 = gm0 & 2047;
                const int gm1 = gm0 + 8;
                const int b1 = gm1 >> 11, s1 = gm1 & 2047;
                const size_t o0 = (((size_t)(b0 * NH + hh) * SEQ + s0) * HD) + dd;
                const size_t o1 = (((size_t)(b1 * NH + hh) * SEQ + s1) * HD) + dd;
                if (which == 2) {
                    float h0 = __bfloat162float(__float2bfloat16(v0.x));
                    float h1 = __bfloat162float(__float2bfloat16(v0.y));
                    float h2 = __bfloat162float(__float2bfloat16(v1.x));
                    float h3 = __bfloat162float(__float2bfloat16(v1.y));
                    *(uint32_t*)(g_vhi + o0) = packbf(v0.x, v0.y);
                    *(uint32_t*)(g_vlo + o0) = packbf(v0.x - h0, v0.y - h1);
                    *(uint32_t*)(g_vhi + o1) = packbf(v1.x, v1.y);
                    *(uint32_t*)(g_vlo + o1) = packbf(v1.x - h2, v1.y - h3);
                } else {
                    float* tgt = (which == 0) ? g_q : g_k;
                    *(float2*)(tgt + o0) = v0;
                    *(float2*)(tgt + o1) = v1;
                }
            }
        }
    }
}

// =================================================================
// RoPE: table once (double precision), then fp32 apply + bf16 split.
// =================================================================
__global__ void rope_table()
{
    const int s = blockIdx.x, d = threadIdx.x;
    const int i = d >> 1;
    const double ang = exp(-((double)(2 * i) / 2048.0) * 9.210340371976184);
    const double fr = (double)s * ang;
    g_cs[s * HD + d] = (float)cos(fr);
    g_sn[s * HD + d] = (float)sin(fr);
}

__global__ void rope_apply()
{
    __shared__ float rq[HD], rk[HD];
    const int row = blockIdx.x;            // (b*NH+h)*SEQ + s
    const int s = row & (SEQ - 1);
    const int d = threadIdx.x;
    rq[d] = g_q[(size_t)row * HD + d];
    rk[d] = g_k[(size_t)row * HD + d];
    __syncthreads();

    const float c  = g_cs[s * HD + d];
    const float sn = g_sn[s * HD + d];
    float oq, ok;
    if (d < 64) {
        oq = c * rq[d] - sn * rq[2 * d + 1];
        ok = c * rk[d] - sn * rk[2 * d + 1];
    } else {
        const int j = d - 64;
        oq = c * rq[d] + sn * rq[2 * j];
        ok = c * rk[d] + sn * rk[2 * j];
    }
    const float qs = oq * 0.08838834764831845f;   // fold 1/sqrt(HD)
    const size_t idx = (size_t)row * HD + d;
    __nv_bfloat16 qh = __float2bfloat16(qs);
    g_qhi[idx] = qh;
    g_qlo[idx] = __float2bfloat16(qs - __bfloat162float(qh));
    __nv_bfloat16 kh = __float2bfloat16(ok);
    g_khi[idx] = kh;
    g_klo[idx] = __float2bfloat16(ok - __bfloat162float(kh));
}

// =================================================================
// MMA flash attention, bf16x3, Q fragments hoisted to registers.
// =================================================================
#define AKB   32
#define QROWB 272
#define PROWB 80
#define KSTGB (AKB * QROWB)
#define OFF_QHI 0
#define OFF_QLO 34816
#define OFF_KHI 69632
#define OFF_KLO (OFF_KHI + 2 * KSTGB)
#define OFF_VHI (OFF_KLO + 2 * KSTGB)
#define OFF_VLO (OFF_VHI + 2 * KSTGB)
#define OFF_PHI (OFF_VLO + 2 * KSTGB)
#define OFF_PLO (OFF_PHI + 128 * PROWB)
#define OFF_MSK (OFF_PLO + 128 * PROWB)
#define ATTN_SMEM (OFF_MSK + 128)

__global__ void __launch_bounds__(256, 1)
attn_mma(const int* __restrict__ mask)
{
    extern __shared__ char smem[];
    const uint32_t sb = smem_u32(smem);
    const int tid = threadIdx.x;
    const int lane = tid & 31, wm = tid >> 5;
    const int q0 = blockIdx.x * 128;
    const int h = blockIdx.y, b = blockIdx.z;
    const size_t bh = ((size_t)b * NH + h) * SEQ;

    // ---- load Q tile (hi+lo) ----
    {
        const char* gqh = (const char*)(g_qhi + (bh + q0) * HD);
        const char* gql = (const char*)(g_qlo + (bh + q0) * HD);
#pragma unroll
        for (int i = 0; i < 8; ++i) {
            const int c = tid + i * 256;
            const int row = c >> 4, seg = (c & 15) * 16;
            CP_ASYNC16(sb + OFF_QHI + row * QROWB + seg, gqh + (size_t)row * 256 + seg);
            CP_ASYNC16(sb + OFF_QLO + row * QROWB + seg, gql + (size_t)row * 256 + seg);
        }
        CP_COMMIT();
    }
    auto loadKV = [&](int kt) {
        const int st = kt & 1;
        const char* gkh = (const char*)(g_khi + (bh + kt * AKB) * HD);
        const char* gkl = (const char*)(g_klo + (bh + kt * AKB) * HD);
        const char* gvh = (const char*)(g_vhi + (bh + kt * AKB) * HD);
        const char* gvl = (const char*)(g_vlo + (bh + kt * AKB) * HD);
#pragma unroll
        for (int i = 0; i < 2; ++i) {
            const int c = tid + i * 256;
            const int row = c >> 4, seg = (c & 15) * 16;
            const uint32_t so = st * KSTGB + row * QROWB + seg;
            const size_t go = (size_t)row * 256 + seg;
            CP_ASYNC16(sb + OFF_KHI + so, gkh + go);
            CP_ASYNC16(sb + OFF_KLO + so, gkl + go);
            CP_ASYNC16(sb + OFF_VHI + so, gvh + go);
            CP_ASYNC16(sb + OFF_VLO + so, gvl + go);
        }
        CP_COMMIT();
    };
    loadKV(0);

    const int r0 = lane >> 2;
    const uint32_t qoff = (wm * 16 + (lane & 15)) * QROWB + ((lane >> 4) << 4);
    const uint32_t kfr = (((lane >> 4) << 3) + (lane & 7)) * QROWB + (((lane >> 3) & 1) << 4);
    const uint32_t poff = (wm * 16 + (lane & 15)) * PROWB + ((lane >> 4) << 4);
    const uint32_t vfr = (lane & 15) * QROWB + (((lane >> 4) << 3) << 1);

    // ---- hoist Q fragments into registers ----
    CP_WAIT1();            // Q group done (KV0 may be pending)
    __syncthreads();
    uint32_t qh[8][4], ql[8][4];
#pragma unroll
    for (int ks = 0; ks < 8; ++ks) {
        ldsm4(qh[ks], sb + OFF_QHI + qoff + ks * 32);
        ldsm4(ql[ks], sb + OFF_QLO + qoff + ks * 32);
    }

    float o[16][4];
#pragma unroll
    for (int t = 0; t < 16; ++t)
#pragma unroll
        for (int j = 0; j < 4; ++j) o[t][j] = 0.f;
    float m0 = -INFINITY, m1 = -INFINITY, l0 = 0.f, l1 = 0.f;

    float* msk = (float*)(smem + OFF_MSK);

    for (int kt = 0; kt < SEQ / AKB; ++kt) {
        __syncthreads();
        if (kt + 1 < SEQ / AKB) loadKV(kt + 1);
        if (tid < AKB) msk[tid] = (float)mask[b * SEQ + kt * AKB + tid];
        if (kt + 1 < SEQ / AKB) { CP_WAIT1(); } else { CP_WAIT0(); }
        __syncthreads();

        const uint32_t kbh = sb + OFF_KHI + (kt & 1) * KSTGB;
        const uint32_t kbl = sb + OFF_KLO + (kt & 1) * KSTGB;

        // ---- S = Q K^T (bf16x3) ----
        float s[4][4];
#pragma unroll
        for (int t = 0; t < 4; ++t)
#pragma unroll
            for (int j = 0; j < 4; ++j) s[t][j] = 0.f;
#pragma unroll
        for (int ks = 0; ks < 8; ++ks) {
            uint32_t kh[2][4], kl[2][4];
#pragma unroll
            for (int nb = 0; nb < 2; ++nb) {
                ldsm4(kh[nb], kbh + nb * 16 * QROWB + kfr + ks * 32);
                ldsm4(kl[nb], kbl + nb * 16 * QROWB + kfr + ks * 32);
            }
#pragma unroll
            for (int t = 0; t < 4; ++t) {
                const int nb = t >> 1, off = (t & 1) * 2;
                mma_bf16(s[t], qh[ks], &kh[nb][off]);
                mma_bf16(s[t], qh[ks], &kl[nb][off]);
                mma_bf16(s[t], ql[ks], &kh[nb][off]);
            }
        }

        // ---- online softmax (rows in-quad) ----
        float rm0 = -INFINITY, rm1 = -INFINITY;
#pragma unroll
        for (int t = 0; t < 4; ++t) {
            const int c = t * 8 + (lane & 3) * 2;
            const float k0 = msk[c], k1 = msk[c + 1];
            if (k0 == 0.f) { s[t][0] = -1e9f; s[t][2] = -1e9f; }
            if (k1 == 0.f) { s[t][1] = -1e9f; s[t][3] = -1e9f; }
            rm0 = fmaxf(rm0, fmaxf(s[t][0], s[t][1]));
            rm1 = fmaxf(rm1, fmaxf(s[t][2], s[t][3]));
        }
        rm0 = fmaxf(rm0, __shfl_xor_sync(0xffffffffu, rm0, 1));
        rm0 = fmaxf(rm0, __shfl_xor_sync(0xffffffffu, rm0, 2));
        rm1 = fmaxf(rm1, __shfl_xor_sync(0xffffffffu, rm1, 1));
        rm1 = fmaxf(rm1, __shfl_xor_sync(0xffffffffu, rm1, 2));
        const float mn0 = fmaxf(m0, rm0);
        const float mn1 = fmaxf(m1, rm1);
        const float sc0 = (m0 == -INFINITY) ? 0.f : __expf(m0 - mn0);
        const float sc1 = (m1 == -INFINITY) ? 0.f : __expf(m1 - mn1);

        float rs0 = 0.f, rs1 = 0.f;
#pragma unroll
        for (int t = 0; t < 4; ++t) {
            const int c = t * 8 + (lane & 3) * 2;
            const float e00 = __expf(s[t][0] - mn0);
            const float e01 = __expf(s[t][1] - mn0);
            const float e10 = __expf(s[t][2] - mn1);
            const float e11 = __expf(s[t][3] - mn1);
            rs0 += e00 + e01;
            rs1 += e10 + e11;
            const float h00 = __bfloat162float(__float2bfloat16(e00));
            const float h01 = __bfloat162float(__float2bfloat16(e01));
            const float h10 = __bfloat162float(__float2bfloat16(e10));
            const float h11 = __bfloat162float(__float2bfloat16(e11));
            char* p0 = smem + (wm * 16 + r0) * PROWB + c * 2;
            char* p1 = smem + (wm * 16 + r0 + 8) * PROWB + c * 2;
            *(uint32_t*)(p0 + OFF_PHI) = packbf(e00, e01);
            *(uint32_t*)(p0 + OFF_PLO) = packbf(e00 - h00, e01 - h01);
            *(uint32_t*)(p1 + OFF_PHI) = packbf(e10, e11);
            *(uint32_t*)(p1 + OFF_PLO) = packbf(e10 - h10, e11 - h11);
        }
        rs0 += __shfl_xor_sync(0xffffffffu, rs0, 1);
        rs0 += __shfl_xor_sync(0xffffffffu, rs0, 2);
        rs1 += __shfl_xor_sync(0xffffffffu, rs1, 1);
        rs1 += __shfl_xor_sync(0xffffffffu, rs1, 2);
        l0 = l0 * sc0 + rs0; m0 = mn0;
        l1 = l1 * sc1 + rs1; m1 = mn1;

#pragma unroll
        for (int t = 0; t < 16; ++t) {
            o[t][0] *= sc0; o[t][1] *= sc0;
            o[t][2] *= sc1; o[t][3] *= sc1;
        }
        __syncwarp();

        // ---- O += P V (bf16x3) ----
        const uint32_t vbh = sb + OFF_VHI + (kt & 1) * KSTGB;
        const uint32_t vbl = sb + OFF_VLO + (kt & 1) * KSTGB;
#pragma unroll
        for (int ks = 0; ks < 2; ++ks) {
            uint32_t ph[4], pl[4];
            ldsm4(ph, sb + OFF_PHI + poff + ks * 32);
            ldsm4(pl, sb + OFF_PLO + poff + ks * 32);
#pragma unroll
            for (int nb = 0; nb < 8; ++nb) {
                uint32_t vh[4], vl[4];
                const uint32_t va = (ks * 16) * QROWB + vfr + nb * 32;
                ldsm4t(vh, vbh + va);
                ldsm4t(vl, vbl + va);
#pragma unroll
                for (int half = 0; half < 2; ++half) {
                    const int t = nb * 2 + half;
                    const int off = half * 2;
                    mma_bf16(o[t], ph, &vh[off]);
                    mma_bf16(o[t], ph, &vl[off]);
                    mma_bf16(o[t], pl, &vh[off]);
                }
            }
        }
    }

    // ---- epilogue: normalize, split to bf16 hi/lo, store ----
    const float inv0 = 1.f / l0;
    const float inv1 = 1.f / l1;
    const size_t row0 = ((size_t)b * SEQ + q0 + wm * 16 + r0) * EMB + h * HD;
    const size_t row1 = row0 + (size_t)8 * EMB;
#pragma unroll
    for (int t = 0; t < 16; ++t) {
        const int c = t * 8 + (lane & 3) * 2;
        const float v0 = o[t][0] * inv0, v1 = o[t][1] * inv0;
        const float v2 = o[t][2] * inv1, v3 = o[t][3] * inv1;
        const float h0 = __bfloat162float(__float2bfloat16(v0));
        const float h1 = __bfloat162float(__float2bfloat16(v1));
        const float h2 = __bfloat162float(__float2bfloat16(v2));
        const float h3 = __bfloat162float(__float2bfloat16(v3));
        *(uint32_t*)(g_ahi + row0 + c) = packbf(v0, v1);
        *(uint32_t*)(g_alo + row0 + c) = packbf(v0 - h0, v1 - h1);
        *(uint32_t*)(g_ahi + row1 + c) = packbf(v2, v3);
        *(uint32_t*)(g_alo + row1 + c) = packbf(v2 - h2, v3 - h3);
    }
}

// =================================================================
extern "C" void kernel_launch(void* const* d_in, const int* in_sizes, int n_in,
                              void* d_out, int out_size)
{
    const float* X    = (const float*)d_in[0];
    const int*   mask = (const int*)d_in[1];
    const float* Wqkv = (const float*)d_in[2];
    const float* bqkv = (const float*)d_in[3];
    const float* Wo   = (const float*)d_in[4];
    const float* bo   = (const float*)d_in[5];
    float* out = (float*)d_out;

    __nv_bfloat16 *ahi, *alo, *w1hi, *w1lo, *w2hi, *w2lo;
    cudaGetSymbolAddress((void**)&ahi,  g_ahi);
    cudaGetSymbolAddress((void**)&alo,  g_alo);
    cudaGetSymbolAddress((void**)&w1hi, g_w1hi);
    cudaGetSymbolAddress((void**)&w1lo, g_w1lo);
    cudaGetSymbolAddress((void**)&w2hi, g_w2hi);
    cudaGetSymbolAddress((void**)&w2lo, g_w2lo);

    cudaFuncSetAttribute(gemm_mma<0>, cudaFuncAttributeMaxDynamicSharedMemorySize, GEMM_SMEM);
    cudaFuncSetAttribute(gemm_mma<1>, cudaFuncAttributeMaxDynamicSharedMemorySize, GEMM_SMEM);
    cudaFuncSetAttribute(attn_mma, cudaFuncAttributeMaxDynamicSharedMemorySize, ATTN_SMEM);

    // 1) conversions + rope table
    cvt_split<<<(MROWS * GK) / 1024, 256>>>(X, ahi, alo, MROWS * GK);
    cvt_split<<<(NQKV * GK) / 1024, 256>>>(Wqkv, w1hi, w1lo, NQKV * GK);
    cvt_split<<<(EMB * GK) / 1024, 256>>>(Wo, w2hi, w2lo, EMB * GK);
    rope_table<<<SEQ, HD>>>();

    // 2) QKV projection: CTA 128x256
    gemm_mma<1><<<dim3(NQKV / 256, MROWS / 128), 256, GEMM_SMEM>>>(
        ahi, alo, w1hi, w1lo, bqkv, nullptr, NQKV);

    // 3) RoPE + Q-scale + bf16 split
    rope_apply<<<BATCH * NH * SEQ, HD>>>();

    // 4) MMA flash attention -> writes g_ahi/g_alo directly
    attn_mma<<<dim3(SEQ / 128, NH, BATCH), 256, ATTN_SMEM>>>(mask);

    // 5) output projection
    gemm_mma<0><<<dim3(EMB / 256, MROWS / 128), 256, GEMM_SMEM>>>(
        ahi, alo, w2hi, w2lo, bo, out, EMB);
}